// round 8
// baseline (speedup 1.0000x reference)
#include <cuda_runtime.h>
#include <cuda_bf16.h>
#include <stdint.h>
#include <math.h>

#define NB 4
#define NR 32
#define NC 512
#define NE 512
#define NH 8
#define ND 64
#define NTOK (NB*NR*NC)          // 65536 tokens
#define EPSV 1e-6f

// ---------------- scratch (__device__ globals; no allocation allowed) ------
__device__ float         g_q   [(size_t)NTOK*NE];
__device__ float         g_k   [(size_t)NTOK*NE];
__device__ float         g_v   [(size_t)NTOK*NE];
__device__ __nv_bfloat16 g_xhi [(size_t)NTOK*NE];
__device__ __nv_bfloat16 g_xlo [(size_t)NTOK*NE];
__device__ __nv_bfloat16 g_ohhi[(size_t)NTOK*NE];
__device__ __nv_bfloat16 g_ohlo[(size_t)NTOK*NE];
__device__ __nv_bfloat16 g_whi [4][NE*NE];
__device__ __nv_bfloat16 g_wlo [4][NE*NE];

// ---------------- PTX helpers (baseline ISA only — no sm_103a features) ----
__device__ __forceinline__ uint32_t smem_u32(const void* p) {
    uint32_t a;
    asm("{ .reg .u64 t; cvta.to.shared.u64 t, %1; cvt.u32.u64 %0, t; }"
        : "=r"(a) : "l"(p));
    return a;
}
#define LDSM4(r0,r1,r2,r3,addr) \
    asm volatile("ldmatrix.sync.aligned.m8n8.x4.shared.b16 {%0,%1,%2,%3}, [%4];" \
                 : "=r"(r0),"=r"(r1),"=r"(r2),"=r"(r3) : "r"(addr))

__device__ __forceinline__ void mma16816(float* d, const uint32_t* a,
                                         const uint32_t* b) {
    asm volatile(
        "mma.sync.aligned.m16n8k16.row.col.f32.bf16.bf16.f32 "
        "{%0,%1,%2,%3}, {%4,%5,%6,%7}, {%8,%9}, {%0,%1,%2,%3};"
        : "+f"(d[0]), "+f"(d[1]), "+f"(d[2]), "+f"(d[3])
        : "r"(a[0]), "r"(a[1]), "r"(a[2]), "r"(a[3]), "r"(b[0]), "r"(b[1]));
}

#define CP_ASYNC16(dst, src) \
    asm volatile("cp.async.cg.shared.global [%0], [%1], 16;" :: "r"(dst), "l"(src))
#define CP_COMMIT() asm volatile("cp.async.commit_group;" ::: "memory")
#define CP_WAIT2()  asm volatile("cp.async.wait_group 2;" ::: "memory")

// packed f32x2 helpers
__device__ __forceinline__ unsigned long long ffma2(unsigned long long a,
                                                    unsigned long long b,
                                                    unsigned long long c) {
    unsigned long long d;
    asm("fma.rn.f32x2 %0, %1, %2, %3;" : "=l"(d) : "l"(a), "l"(b), "l"(c));
    return d;
}
__device__ __forceinline__ unsigned long long pack2(float lo, float hi) {
    unsigned long long d;
    asm("mov.b64 %0, {%1, %2};" : "=l"(d) : "f"(lo), "f"(hi));
    return d;
}
__device__ __forceinline__ float2 unpack2(unsigned long long v) {
    float lo, hi;
    asm("mov.b64 {%0, %1}, %2;" : "=f"(lo), "=f"(hi) : "l"(v));
    return make_float2(lo, hi);
}

// ---------------------------------------------------------------------------
// Split-bf16 tensor-core GEMM (mma.sync + 4-stage cp.async pipeline).
//   Y[tok,512] = A[tok,512] @ W[512,512]^T + bias   (optional elu+1)
// computed as A_hi@W_hi + A_hi@W_lo + A_lo@W_hi with fp32 accumulation.
// CTA: 128 tokens x 128 cols, K-tile 32, 48 K-iters (3 terms x 16).
// 8 warps (2M x 4N), warp tile 64x32. blockIdx.z selects projection.
// ---------------------------------------------------------------------------
struct ProjArg {
    const __nv_bfloat16* whi;
    const __nv_bfloat16* wlo;
    const float* bias;
    float* out;
    int act;
};

#define STAGES 4
#define KT 32
#define KPAD 40                        // 32 + 8 pad: conflict-free ldmatrix
#define STAGE_ELEMS (128*KPAD)         // bf16 elems per array per stage
#define STAGE_BYTES (2*STAGE_ELEMS*2)  // A + B, bytes
#define GSMEM_BYTES (STAGES*STAGE_BYTES)   // 81920

__device__ __forceinline__ void issue_tile(int nt, uint32_t slot,
                                           const __nv_bfloat16* __restrict__ As,
                                           const __nv_bfloat16* __restrict__ Bs,
                                           int tokb, int colb, int tid)
{
    const int kk = (nt & 15) * KT;
    #pragma unroll
    for (int u = 0; u < 2; ++u) {
        const int idx = tid + u * 256;        // 0..511
        const int row = idx >> 2;             // 0..127
        const int seg = (idx & 3) * 8;        // bf16 col offset in tile
        const uint32_t soff = (uint32_t)(row * KPAD + seg) * 2;
        CP_ASYNC16(slot + soff,
                   As + (size_t)(tokb + row) * NE + kk + seg);
        CP_ASYNC16(slot + STAGE_ELEMS * 2 + soff,
                   Bs + (size_t)(colb + row) * NE + kk + seg);
    }
}

__global__ void __launch_bounds__(256, 2)
mma_gemm(const __nv_bfloat16* __restrict__ ahi,
         const __nv_bfloat16* __restrict__ alo,
         ProjArg p0, ProjArg p1, ProjArg p2)
{
    extern __shared__ __align__(16) char gsm[];

    const int tid  = threadIdx.x;
    const int wid  = tid >> 5, lane = tid & 31;
    const int wm   = wid >> 2;            // 0..1  (M)
    const int wn   = wid & 3;             // 0..3  (N)
    const int tokb = blockIdx.y * 128;
    const int colb = blockIdx.x * 128;

    const ProjArg pr = (blockIdx.z == 0) ? p0 : (blockIdx.z == 1) ? p1 : p2;
    const __nv_bfloat16* Aterm[3] = { ahi, ahi, alo };
    const __nv_bfloat16* Bterm[3] = { pr.whi, pr.wlo, pr.whi };

    const uint32_t sb = smem_u32(gsm);

    // ldmatrix per-thread invariant offsets (bf16 elems)
    const int offA = (wm * 64 + (lane & 15)) * KPAD + ((lane >> 4) << 3);
    const int offB = (wn * 32 + (lane & 7) + ((lane & 16) >> 1)) * KPAD + (lane & 8);

    float acc[4][4][4];
    #pragma unroll
    for (int i = 0; i < 4; ++i)
        #pragma unroll
        for (int j = 0; j < 4; ++j)
            #pragma unroll
            for (int q = 0; q < 4; ++q) acc[i][j][q] = 0.f;

    // prologue: issue tiles 0..STAGES-2 (all term 0)
    #pragma unroll
    for (int s = 0; s < STAGES - 1; ++s) {
        issue_tile(s, sb + s * STAGE_BYTES, Aterm[0], Bterm[0], tokb, colb, tid);
        CP_COMMIT();
    }

    #pragma unroll 1
    for (int kt = 0; kt < 48; ++kt) {
        CP_WAIT2();                 // tile kt landed (for this thread)
        __syncthreads();            // visible to all; prev consumption done

        // refill the slot freed last iteration with tile kt+STAGES-1
        {
            const int nt = kt + STAGES - 1;
            if (nt < 48) {
                const int term = nt >> 4;
                issue_tile(nt, sb + (nt & (STAGES - 1)) * STAGE_BYTES,
                           Aterm[term], Bterm[term], tokb, colb, tid);
            }
            CP_COMMIT();            // always commit to keep group accounting
        }

        // compute on slot kt%STAGES
        const uint32_t aBase = sb + (kt & (STAGES - 1)) * STAGE_BYTES + offA * 2;
        const uint32_t bBase = aBase - offA * 2 + STAGE_ELEMS * 2 + offB * 2;
        #pragma unroll
        for (int ks = 0; ks < 2; ++ks) {
            uint32_t af[4][4], bfr[2][4];
            #pragma unroll
            for (int mi = 0; mi < 4; ++mi)
                LDSM4(af[mi][0], af[mi][1], af[mi][2], af[mi][3],
                      aBase + (mi * 16 * KPAD + ks * 16) * 2);
            #pragma unroll
            for (int nj = 0; nj < 2; ++nj)
                LDSM4(bfr[nj][0], bfr[nj][1], bfr[nj][2], bfr[nj][3],
                      bBase + (nj * 16 * KPAD + ks * 16) * 2);
            #pragma unroll
            for (int mi = 0; mi < 4; ++mi)
                #pragma unroll
                for (int ni = 0; ni < 4; ++ni)
                    mma16816(acc[mi][ni], af[mi], &bfr[ni >> 1][(ni & 1) * 2]);
        }
    }

    // ---- epilogue: bias (+ elu+1), fp32 stores ----
    const int g  = lane >> 2;
    const int tg = lane & 3;
    #pragma unroll
    for (int ni = 0; ni < 4; ++ni) {
        const int col = colb + wn * 32 + ni * 8 + tg * 2;
        const float2 bv = *(const float2*)&pr.bias[col];
        #pragma unroll
        for (int mi = 0; mi < 4; ++mi) {
            const int row0 = tokb + wm * 64 + mi * 16 + g;
            float o0 = acc[mi][ni][0] + bv.x;
            float o1 = acc[mi][ni][1] + bv.y;
            float o2 = acc[mi][ni][2] + bv.x;
            float o3 = acc[mi][ni][3] + bv.y;
            if (pr.act) {
                o0 = (o0 > 0.f) ? (o0 + 1.f) : expf(o0);
                o1 = (o1 > 0.f) ? (o1 + 1.f) : expf(o1);
                o2 = (o2 > 0.f) ? (o2 + 1.f) : expf(o2);
                o3 = (o3 > 0.f) ? (o3 + 1.f) : expf(o3);
            }
            *(float2*)(pr.out + (size_t)row0 * NE + col)       = make_float2(o0, o1);
            *(float2*)(pr.out + (size_t)(row0 + 8) * NE + col) = make_float2(o2, o3);
        }
    }
}

// ---------------------------------------------------------------------------
// fp32 -> (bf16 hi, bf16 lo) elementwise split
// ---------------------------------------------------------------------------
__global__ void split_kernel(const float* __restrict__ src,
                             __nv_bfloat16* __restrict__ hi,
                             __nv_bfloat16* __restrict__ lo, int n4)
{
    int i = blockIdx.x * blockDim.x + threadIdx.x;
    if (i >= n4) return;
    float4 v = ((const float4*)src)[i];
    __nv_bfloat16 h0 = __float2bfloat16(v.x), h1 = __float2bfloat16(v.y);
    __nv_bfloat16 h2 = __float2bfloat16(v.z), h3 = __float2bfloat16(v.w);
    __nv_bfloat16 l0 = __float2bfloat16(v.x - __bfloat162float(h0));
    __nv_bfloat16 l1 = __float2bfloat16(v.y - __bfloat162float(h1));
    __nv_bfloat16 l2 = __float2bfloat16(v.z - __bfloat162float(h2));
    __nv_bfloat16 l3 = __float2bfloat16(v.w - __bfloat162float(h3));
    __nv_bfloat162 a = __halves2bfloat162(h0, h1), b = __halves2bfloat162(h2, h3);
    __nv_bfloat162 c = __halves2bfloat162(l0, l1), d = __halves2bfloat162(l2, l3);
    ((uint2*)hi)[i] = make_uint2(*(uint32_t*)&a, *(uint32_t*)&b);
    ((uint2*)lo)[i] = make_uint2(*(uint32_t*)&c, *(uint32_t*)&d);
}

// ---------------------------------------------------------------------------
// Linear attention core (packed f32x2 math), bf16 hi/lo output for O GEMM.
// ---------------------------------------------------------------------------
__global__ void __launch_bounds__(256)
linattn_kernel(const float* __restrict__ gq,
               const float* __restrict__ gk,
               const float* __restrict__ gv,
               __nv_bfloat16* __restrict__ gohhi,
               __nv_bfloat16* __restrict__ gohlo)
{
    const int g  = blockIdx.x;
    const int h  = g & (NH - 1);
    const int br = g >> 3;
    const size_t rowbase = (size_t)br * NC;
    const int colbase = h * ND;

    __shared__ float sk[32][64];
    __shared__ float sv[32][64];
    __shared__ float sktv[64][64];
    __shared__ float sksum[64];
    __shared__ float sq[16][64];

    const int tid = threadIdx.x;

    // ---- Phase 1: ktv = K^T V, ksum ----
    const int d0 = (tid >> 4) << 2;
    const int e0 = (tid & 15) << 2;
    unsigned long long acc[4][2];
    #pragma unroll
    for (int i = 0; i < 4; ++i) { acc[i][0] = 0ULL; acc[i][1] = 0ULL; }
    float ksum = 0.0f;

    for (int ct = 0; ct < NC / 32; ++ct) {
        const int c0 = ct * 32;
        #pragma unroll
        for (int u = 0; u < 2; ++u) {
            int idx = tid + u * 256;
            int rr  = idx >> 4;
            int qq  = (idx & 15) << 2;
            size_t goff = (rowbase + c0 + rr) * (size_t)NE + colbase + qq;
            *(float4*)&sk[rr][qq] = *(const float4*)(gk + goff);
            *(float4*)&sv[rr][qq] = *(const float4*)(gv + goff);
        }
        __syncthreads();

        #pragma unroll 8
        for (int cc = 0; cc < 32; ++cc) {
            float4 k4 = *(const float4*)&sk[cc][d0];
            ulonglong2 vv = *(const ulonglong2*)&sv[cc][e0];
            float kv[4] = {k4.x, k4.y, k4.z, k4.w};
            #pragma unroll
            for (int i = 0; i < 4; ++i) {
                unsigned long long kp = pack2(kv[i], kv[i]);
                acc[i][0] = ffma2(kp, vv.x, acc[i][0]);
                acc[i][1] = ffma2(kp, vv.y, acc[i][1]);
            }
        }
        if (tid < 64) {
            #pragma unroll 8
            for (int cc = 0; cc < 32; ++cc) ksum += sk[cc][tid];
        }
        __syncthreads();
    }

    #pragma unroll
    for (int i = 0; i < 4; ++i) {
        float2 p0 = unpack2(acc[i][0]);
        float2 p1 = unpack2(acc[i][1]);
        *(float4*)&sktv[d0 + i][e0] = make_float4(p0.x, p0.y, p1.x, p1.y);
    }
    if (tid < 64) sksum[tid] = ksum;
    __syncthreads();

    // ---- Phase 2: oh = (Q @ ktv) / (Q . ksum + eps) ----
    const int r   = tid >> 4;
    const int e20 = (tid & 15) << 2;
    for (int ct = 0; ct < NC / 16; ++ct) {
        const int c0 = ct * 16;
        {
            size_t goff = (rowbase + c0 + r) * (size_t)NE + colbase + e20;
            *(float4*)&sq[r][e20] = *(const float4*)(gq + goff);
        }
        __syncthreads();

        unsigned long long a2[2] = {0ULL, 0ULL};
        float zacc = 0.0f;
        #pragma unroll
        for (int d = 0; d < 64; ++d) {
            float qv = sq[r][d];
            unsigned long long qp = pack2(qv, qv);
            ulonglong2 kt = *(const ulonglong2*)&sktv[d][e20];
            a2[0] = ffma2(qp, kt.x, a2[0]);
            a2[1] = ffma2(qp, kt.y, a2[1]);
            zacc  = fmaf(qv, sksum[d], zacc);
        }
        float z = 1.0f / (zacc + EPSV);
        float2 p0 = unpack2(a2[0]);
        float2 p1 = unpack2(a2[1]);
        float o0 = p0.x * z, o1 = p0.y * z, o2 = p1.x * z, o3 = p1.y * z;

        __nv_bfloat16 h0 = __float2bfloat16(o0), h1 = __float2bfloat16(o1);
        __nv_bfloat16 h2 = __float2bfloat16(o2), h3 = __float2bfloat16(o3);
        __nv_bfloat16 l0 = __float2bfloat16(o0 - __bfloat162float(h0));
        __nv_bfloat16 l1 = __float2bfloat16(o1 - __bfloat162float(h1));
        __nv_bfloat16 l2 = __float2bfloat16(o2 - __bfloat162float(h2));
        __nv_bfloat16 l3 = __float2bfloat16(o3 - __bfloat162float(h3));
        __nv_bfloat162 hh0 = __halves2bfloat162(h0, h1), hh1 = __halves2bfloat162(h2, h3);
        __nv_bfloat162 ll0 = __halves2bfloat162(l0, l1), ll1 = __halves2bfloat162(l2, l3);

        size_t ooff = (rowbase + c0 + r) * (size_t)NE + colbase + e20;
        *(uint2*)(gohhi + ooff) = make_uint2(*(uint32_t*)&hh0, *(uint32_t*)&hh1);
        *(uint2*)(gohlo + ooff) = make_uint2(*(uint32_t*)&ll0, *(uint32_t*)&ll1);
        __syncthreads();
    }
}

// ---------------------------------------------------------------------------
extern "C" void kernel_launch(void* const* d_in, const int* in_sizes, int n_in,
                              void* d_out, int out_size)
{
    const float* x  = (const float*)d_in[0];
    const float* Wq = (const float*)d_in[1];
    const float* bq = (const float*)d_in[2];
    const float* Wk = (const float*)d_in[3];
    const float* bk = (const float*)d_in[4];
    const float* Wv = (const float*)d_in[5];
    const float* bv = (const float*)d_in[6];
    const float* Wo = (const float*)d_in[7];
    const float* bo = (const float*)d_in[8];
    float* out = (float*)d_out;

    void *pq, *pk, *pv, *pxhi, *pxlo, *pohhi, *pohlo, *pwhi, *pwlo;
    cudaGetSymbolAddress(&pq, g_q);
    cudaGetSymbolAddress(&pk, g_k);
    cudaGetSymbolAddress(&pv, g_v);
    cudaGetSymbolAddress(&pxhi, g_xhi);
    cudaGetSymbolAddress(&pxlo, g_xlo);
    cudaGetSymbolAddress(&pohhi, g_ohhi);
    cudaGetSymbolAddress(&pohlo, g_ohlo);
    cudaGetSymbolAddress(&pwhi, g_whi);
    cudaGetSymbolAddress(&pwlo, g_wlo);

    __nv_bfloat16* whi = (__nv_bfloat16*)pwhi;
    __nv_bfloat16* wlo = (__nv_bfloat16*)pwlo;

    // allow 80KB dynamic smem (idempotent; capture-safe, not a stream op)
    cudaFuncSetAttribute(mma_gemm, cudaFuncAttributeMaxDynamicSharedMemorySize,
                         GSMEM_BYTES);

    // 1) splits
    {
        int n4 = (NTOK * NE) / 4;
        split_kernel<<<n4 / 256, 256>>>(x, (__nv_bfloat16*)pxhi, (__nv_bfloat16*)pxlo, n4);
        int w4 = (NE * NE) / 4;
        split_kernel<<<w4 / 256, 256>>>(Wq, whi + 0 * NE * NE, wlo + 0 * NE * NE, w4);
        split_kernel<<<w4 / 256, 256>>>(Wk, whi + 1 * NE * NE, wlo + 1 * NE * NE, w4);
        split_kernel<<<w4 / 256, 256>>>(Wv, whi + 2 * NE * NE, wlo + 2 * NE * NE, w4);
        split_kernel<<<w4 / 256, 256>>>(Wo, whi + 3 * NE * NE, wlo + 3 * NE * NE, w4);
    }

    // 2) fused QKV projections (tensor cores, z = proj)
    ProjArg aq = { whi + 0 * NE * NE, wlo + 0 * NE * NE, bq, (float*)pq, 1 };
    ProjArg ak = { whi + 1 * NE * NE, wlo + 1 * NE * NE, bk, (float*)pk, 1 };
    ProjArg av = { whi + 2 * NE * NE, wlo + 2 * NE * NE, bv, (float*)pv, 0 };
    {
        dim3 grid(NE / 128, NTOK / 128, 3);
        mma_gemm<<<grid, 256, GSMEM_BYTES>>>((const __nv_bfloat16*)pxhi,
                                             (const __nv_bfloat16*)pxlo,
                                             aq, ak, av);
    }

    // 3) linear attention (emits bf16 hi/lo for the O GEMM)
    linattn_kernel<<<NB * NR * NH, 256>>>((const float*)pq, (const float*)pk,
                                          (const float*)pv,
                                          (__nv_bfloat16*)pohhi, (__nv_bfloat16*)pohlo);

    // 4) output projection
    ProjArg ao = { whi + 3 * NE * NE, wlo + 3 * NE * NE, bo, out, 0 };
    {
        dim3 grid(NE / 128, NTOK / 128, 1);
        mma_gemm<<<grid, 256, GSMEM_BYTES>>>((const __nv_bfloat16*)pohhi,
                                             (const __nv_bfloat16*)pohlo,
                                             ao, ao, ao);
    }
}

// round 9
// speedup vs baseline: 1.0007x; 1.0007x over previous
#include <cuda_runtime.h>
#include <cuda_bf16.h>
#include <stdint.h>
#include <math.h>

#define NB 4
#define NR 32
#define NC 512
#define NE 512
#define NH 8
#define ND 64
#define NTOK (NB*NR*NC)          // 65536 tokens
#define EPSV 1e-6f

// ---------------- scratch (__device__ globals; no allocation allowed) ------
__device__ float         g_q   [(size_t)NTOK*NE];
__device__ float         g_k   [(size_t)NTOK*NE];
__device__ float         g_v   [(size_t)NTOK*NE];
__device__ __nv_bfloat16 g_xhi [(size_t)NTOK*NE];
__device__ __nv_bfloat16 g_xlo [(size_t)NTOK*NE];
__device__ __nv_bfloat16 g_ohhi[(size_t)NTOK*NE];
__device__ __nv_bfloat16 g_ohlo[(size_t)NTOK*NE];
__device__ __nv_bfloat16 g_whi [4][NE*NE];
__device__ __nv_bfloat16 g_wlo [4][NE*NE];

// ---------------- PTX helpers (baseline ISA only — no sm_103a features) ----
__device__ __forceinline__ uint32_t smem_u32(const void* p) {
    uint32_t a;
    asm("{ .reg .u64 t; cvta.to.shared.u64 t, %1; cvt.u32.u64 %0, t; }"
        : "=r"(a) : "l"(p));
    return a;
}
#define LDSM4(r0,r1,r2,r3,addr) \
    asm volatile("ldmatrix.sync.aligned.m8n8.x4.shared.b16 {%0,%1,%2,%3}, [%4];" \
                 : "=r"(r0),"=r"(r1),"=r"(r2),"=r"(r3) : "r"(addr))

__device__ __forceinline__ void mma16816(float* d, const uint32_t* a,
                                         const uint32_t* b) {
    asm volatile(
        "mma.sync.aligned.m16n8k16.row.col.f32.bf16.bf16.f32 "
        "{%0,%1,%2,%3}, {%4,%5,%6,%7}, {%8,%9}, {%0,%1,%2,%3};"
        : "+f"(d[0]), "+f"(d[1]), "+f"(d[2]), "+f"(d[3])
        : "r"(a[0]), "r"(a[1]), "r"(a[2]), "r"(a[3]), "r"(b[0]), "r"(b[1]));
}

#define CP_ASYNC16(dst, src) \
    asm volatile("cp.async.cg.shared.global [%0], [%1], 16;" :: "r"(dst), "l"(src))
#define CP_COMMIT() asm volatile("cp.async.commit_group;" ::: "memory")
#define CP_WAIT2()  asm volatile("cp.async.wait_group 2;" ::: "memory")

// packed f32x2 helpers
__device__ __forceinline__ unsigned long long ffma2(unsigned long long a,
                                                    unsigned long long b,
                                                    unsigned long long c) {
    unsigned long long d;
    asm("fma.rn.f32x2 %0, %1, %2, %3;" : "=l"(d) : "l"(a), "l"(b), "l"(c));
    return d;
}
__device__ __forceinline__ unsigned long long pack2(float lo, float hi) {
    unsigned long long d;
    asm("mov.b64 %0, {%1, %2};" : "=l"(d) : "f"(lo), "f"(hi));
    return d;
}
__device__ __forceinline__ float2 unpack2(unsigned long long v) {
    float lo, hi;
    asm("mov.b64 {%0, %1}, %2;" : "=f"(lo), "=f"(hi) : "l"(v));
    return make_float2(lo, hi);
}

// ---------------------------------------------------------------------------
// Split-bf16 tensor-core GEMM (mma.sync + 4-stage cp.async pipeline).
//   Y[tok,512] = A[tok,512] @ W[512,512]^T + bias   (optional elu+1)
// computed as A_hi@W_hi + A_hi@W_lo + A_lo@W_hi with fp32 accumulation.
// CTA: 128 tokens x 128 cols, K-tile 32, 48 K-iters (3 terms x 16).
// 8 warps (2M x 4N), warp tile 64x32. blockIdx.z selects projection.
// ---------------------------------------------------------------------------
struct ProjArg {
    const __nv_bfloat16* whi;
    const __nv_bfloat16* wlo;
    const float* bias;
    float* out;
    int act;
};

#define STAGES 4
#define KT 32
#define KPAD 40                        // 32 + 8 pad: conflict-free ldmatrix
#define STAGE_ELEMS (128*KPAD)         // bf16 elems per array per stage
#define STAGE_BYTES (2*STAGE_ELEMS*2)  // A + B, bytes
#define GSMEM_BYTES (STAGES*STAGE_BYTES)   // 81920

__device__ __forceinline__ void issue_tile(int nt, uint32_t slot,
                                           const __nv_bfloat16* __restrict__ As,
                                           const __nv_bfloat16* __restrict__ Bs,
                                           int tokb, int colb, int tid)
{
    const int kk = (nt & 15) * KT;
    #pragma unroll
    for (int u = 0; u < 2; ++u) {
        const int idx = tid + u * 256;        // 0..511
        const int row = idx >> 2;             // 0..127
        const int seg = (idx & 3) * 8;        // bf16 col offset in tile
        const uint32_t soff = (uint32_t)(row * KPAD + seg) * 2;
        CP_ASYNC16(slot + soff,
                   As + (size_t)(tokb + row) * NE + kk + seg);
        CP_ASYNC16(slot + STAGE_ELEMS * 2 + soff,
                   Bs + (size_t)(colb + row) * NE + kk + seg);
    }
}

__global__ void __launch_bounds__(256, 2)
mma_gemm(const __nv_bfloat16* __restrict__ ahi,
         const __nv_bfloat16* __restrict__ alo,
         ProjArg p0, ProjArg p1, ProjArg p2)
{
    extern __shared__ __align__(16) char gsm[];

    const int tid  = threadIdx.x;
    const int wid  = tid >> 5, lane = tid & 31;
    const int wm   = wid >> 2;            // 0..1  (M)
    const int wn   = wid & 3;             // 0..3  (N)
    const int tokb = blockIdx.y * 128;
    const int colb = blockIdx.x * 128;

    const ProjArg pr = (blockIdx.z == 0) ? p0 : (blockIdx.z == 1) ? p1 : p2;
    const __nv_bfloat16* Aterm[3] = { ahi, ahi, alo };
    const __nv_bfloat16* Bterm[3] = { pr.whi, pr.wlo, pr.whi };

    const uint32_t sb = smem_u32(gsm);

    // ldmatrix per-thread invariant offsets (bf16 elems)
    const int offA = (wm * 64 + (lane & 15)) * KPAD + ((lane >> 4) << 3);
    const int offB = (wn * 32 + (lane & 7) + ((lane & 16) >> 1)) * KPAD + (lane & 8);

    float acc[4][4][4];
    #pragma unroll
    for (int i = 0; i < 4; ++i)
        #pragma unroll
        for (int j = 0; j < 4; ++j)
            #pragma unroll
            for (int q = 0; q < 4; ++q) acc[i][j][q] = 0.f;

    // prologue: issue tiles 0..STAGES-2 (all term 0)
    #pragma unroll
    for (int s = 0; s < STAGES - 1; ++s) {
        issue_tile(s, sb + s * STAGE_BYTES, Aterm[0], Bterm[0], tokb, colb, tid);
        CP_COMMIT();
    }

    #pragma unroll 1
    for (int kt = 0; kt < 48; ++kt) {
        CP_WAIT2();                 // tile kt landed (for this thread)
        __syncthreads();            // visible to all; prev consumption done

        // refill the slot freed last iteration with tile kt+STAGES-1
        {
            const int nt = kt + STAGES - 1;
            if (nt < 48) {
                const int term = nt >> 4;
                issue_tile(nt, sb + (nt & (STAGES - 1)) * STAGE_BYTES,
                           Aterm[term], Bterm[term], tokb, colb, tid);
            }
            CP_COMMIT();            // always commit to keep group accounting
        }

        // compute on slot kt%STAGES
        const uint32_t aBase = sb + (kt & (STAGES - 1)) * STAGE_BYTES + offA * 2;
        const uint32_t bBase = aBase - offA * 2 + STAGE_ELEMS * 2 + offB * 2;
        #pragma unroll
        for (int ks = 0; ks < 2; ++ks) {
            uint32_t af[4][4], bfr[2][4];
            #pragma unroll
            for (int mi = 0; mi < 4; ++mi)
                LDSM4(af[mi][0], af[mi][1], af[mi][2], af[mi][3],
                      aBase + (mi * 16 * KPAD + ks * 16) * 2);
            #pragma unroll
            for (int nj = 0; nj < 2; ++nj)
                LDSM4(bfr[nj][0], bfr[nj][1], bfr[nj][2], bfr[nj][3],
                      bBase + (nj * 16 * KPAD + ks * 16) * 2);
            #pragma unroll
            for (int mi = 0; mi < 4; ++mi)
                #pragma unroll
                for (int ni = 0; ni < 4; ++ni)
                    mma16816(acc[mi][ni], af[mi], &bfr[ni >> 1][(ni & 1) * 2]);
        }
    }

    // ---- epilogue: bias (+ elu+1), fp32 stores ----
    const int g  = lane >> 2;
    const int tg = lane & 3;
    #pragma unroll
    for (int ni = 0; ni < 4; ++ni) {
        const int col = colb + wn * 32 + ni * 8 + tg * 2;
        const float2 bv = *(const float2*)&pr.bias[col];
        #pragma unroll
        for (int mi = 0; mi < 4; ++mi) {
            const int row0 = tokb + wm * 64 + mi * 16 + g;
            float o0 = acc[mi][ni][0] + bv.x;
            float o1 = acc[mi][ni][1] + bv.y;
            float o2 = acc[mi][ni][2] + bv.x;
            float o3 = acc[mi][ni][3] + bv.y;
            if (pr.act) {
                o0 = (o0 > 0.f) ? (o0 + 1.f) : expf(o0);
                o1 = (o1 > 0.f) ? (o1 + 1.f) : expf(o1);
                o2 = (o2 > 0.f) ? (o2 + 1.f) : expf(o2);
                o3 = (o3 > 0.f) ? (o3 + 1.f) : expf(o3);
            }
            *(float2*)(pr.out + (size_t)row0 * NE + col)       = make_float2(o0, o1);
            *(float2*)(pr.out + (size_t)(row0 + 8) * NE + col) = make_float2(o2, o3);
        }
    }
}

// ---------------------------------------------------------------------------
// fp32 -> (bf16 hi, bf16 lo) elementwise split
// ---------------------------------------------------------------------------
__global__ void split_kernel(const float* __restrict__ src,
                             __nv_bfloat16* __restrict__ hi,
                             __nv_bfloat16* __restrict__ lo, int n4)
{
    int i = blockIdx.x * blockDim.x + threadIdx.x;
    if (i >= n4) return;
    float4 v = ((const float4*)src)[i];
    __nv_bfloat16 h0 = __float2bfloat16(v.x), h1 = __float2bfloat16(v.y);
    __nv_bfloat16 h2 = __float2bfloat16(v.z), h3 = __float2bfloat16(v.w);
    __nv_bfloat16 l0 = __float2bfloat16(v.x - __bfloat162float(h0));
    __nv_bfloat16 l1 = __float2bfloat16(v.y - __bfloat162float(h1));
    __nv_bfloat16 l2 = __float2bfloat16(v.z - __bfloat162float(h2));
    __nv_bfloat16 l3 = __float2bfloat16(v.w - __bfloat162float(h3));
    __nv_bfloat162 a = __halves2bfloat162(h0, h1), b = __halves2bfloat162(h2, h3);
    __nv_bfloat162 c = __halves2bfloat162(l0, l1), d = __halves2bfloat162(l2, l3);
    ((uint2*)hi)[i] = make_uint2(*(uint32_t*)&a, *(uint32_t*)&b);
    ((uint2*)lo)[i] = make_uint2(*(uint32_t*)&c, *(uint32_t*)&d);
}

// ---------------------------------------------------------------------------
// Linear attention core (packed f32x2 math), bf16 hi/lo output for O GEMM.
// ---------------------------------------------------------------------------
__global__ void __launch_bounds__(256)
linattn_kernel(const float* __restrict__ gq,
               const float* __restrict__ gk,
               const float* __restrict__ gv,
               __nv_bfloat16* __restrict__ gohhi,
               __nv_bfloat16* __restrict__ gohlo)
{
    const int g  = blockIdx.x;
    const int h  = g & (NH - 1);
    const int br = g >> 3;
    const size_t rowbase = (size_t)br * NC;
    const int colbase = h * ND;

    __shared__ float sk[32][64];
    __shared__ float sv[32][64];
    __shared__ float sktv[64][64];
    __shared__ float sksum[64];
    __shared__ float sq[16][64];

    const int tid = threadIdx.x;

    // ---- Phase 1: ktv = K^T V, ksum ----
    const int d0 = (tid >> 4) << 2;
    const int e0 = (tid & 15) << 2;
    unsigned long long acc[4][2];
    #pragma unroll
    for (int i = 0; i < 4; ++i) { acc[i][0] = 0ULL; acc[i][1] = 0ULL; }
    float ksum = 0.0f;

    for (int ct = 0; ct < NC / 32; ++ct) {
        const int c0 = ct * 32;
        #pragma unroll
        for (int u = 0; u < 2; ++u) {
            int idx = tid + u * 256;
            int rr  = idx >> 4;
            int qq  = (idx & 15) << 2;
            size_t goff = (rowbase + c0 + rr) * (size_t)NE + colbase + qq;
            *(float4*)&sk[rr][qq] = *(const float4*)(gk + goff);
            *(float4*)&sv[rr][qq] = *(const float4*)(gv + goff);
        }
        __syncthreads();

        #pragma unroll 8
        for (int cc = 0; cc < 32; ++cc) {
            float4 k4 = *(const float4*)&sk[cc][d0];
            ulonglong2 vv = *(const ulonglong2*)&sv[cc][e0];
            float kv[4] = {k4.x, k4.y, k4.z, k4.w};
            #pragma unroll
            for (int i = 0; i < 4; ++i) {
                unsigned long long kp = pack2(kv[i], kv[i]);
                acc[i][0] = ffma2(kp, vv.x, acc[i][0]);
                acc[i][1] = ffma2(kp, vv.y, acc[i][1]);
            }
        }
        if (tid < 64) {
            #pragma unroll 8
            for (int cc = 0; cc < 32; ++cc) ksum += sk[cc][tid];
        }
        __syncthreads();
    }

    #pragma unroll
    for (int i = 0; i < 4; ++i) {
        float2 p0 = unpack2(acc[i][0]);
        float2 p1 = unpack2(acc[i][1]);
        *(float4*)&sktv[d0 + i][e0] = make_float4(p0.x, p0.y, p1.x, p1.y);
    }
    if (tid < 64) sksum[tid] = ksum;
    __syncthreads();

    // ---- Phase 2: oh = (Q @ ktv) / (Q . ksum + eps) ----
    const int r   = tid >> 4;
    const int e20 = (tid & 15) << 2;
    for (int ct = 0; ct < NC / 16; ++ct) {
        const int c0 = ct * 16;
        {
            size_t goff = (rowbase + c0 + r) * (size_t)NE + colbase + e20;
            *(float4*)&sq[r][e20] = *(const float4*)(gq + goff);
        }
        __syncthreads();

        unsigned long long a2[2] = {0ULL, 0ULL};
        float zacc = 0.0f;
        #pragma unroll
        for (int d = 0; d < 64; ++d) {
            float qv = sq[r][d];
            unsigned long long qp = pack2(qv, qv);
            ulonglong2 kt = *(const ulonglong2*)&sktv[d][e20];
            a2[0] = ffma2(qp, kt.x, a2[0]);
            a2[1] = ffma2(qp, kt.y, a2[1]);
            zacc  = fmaf(qv, sksum[d], zacc);
        }
        float z = 1.0f / (zacc + EPSV);
        float2 p0 = unpack2(a2[0]);
        float2 p1 = unpack2(a2[1]);
        float o0 = p0.x * z, o1 = p0.y * z, o2 = p1.x * z, o3 = p1.y * z;

        __nv_bfloat16 h0 = __float2bfloat16(o0), h1 = __float2bfloat16(o1);
        __nv_bfloat16 h2 = __float2bfloat16(o2), h3 = __float2bfloat16(o3);
        __nv_bfloat16 l0 = __float2bfloat16(o0 - __bfloat162float(h0));
        __nv_bfloat16 l1 = __float2bfloat16(o1 - __bfloat162float(h1));
        __nv_bfloat16 l2 = __float2bfloat16(o2 - __bfloat162float(h2));
        __nv_bfloat16 l3 = __float2bfloat16(o3 - __bfloat162float(h3));
        __nv_bfloat162 hh0 = __halves2bfloat162(h0, h1), hh1 = __halves2bfloat162(h2, h3);
        __nv_bfloat162 ll0 = __halves2bfloat162(l0, l1), ll1 = __halves2bfloat162(l2, l3);

        size_t ooff = (rowbase + c0 + r) * (size_t)NE + colbase + e20;
        *(uint2*)(gohhi + ooff) = make_uint2(*(uint32_t*)&hh0, *(uint32_t*)&hh1);
        *(uint2*)(gohlo + ooff) = make_uint2(*(uint32_t*)&ll0, *(uint32_t*)&ll1);
        __syncthreads();
    }
}

// ---------------------------------------------------------------------------
extern "C" void kernel_launch(void* const* d_in, const int* in_sizes, int n_in,
                              void* d_out, int out_size)
{
    const float* x  = (const float*)d_in[0];
    const float* Wq = (const float*)d_in[1];
    const float* bq = (const float*)d_in[2];
    const float* Wk = (const float*)d_in[3];
    const float* bk = (const float*)d_in[4];
    const float* Wv = (const float*)d_in[5];
    const float* bv = (const float*)d_in[6];
    const float* Wo = (const float*)d_in[7];
    const float* bo = (const float*)d_in[8];
    float* out = (float*)d_out;

    void *pq, *pk, *pv, *pxhi, *pxlo, *pohhi, *pohlo, *pwhi, *pwlo;
    cudaGetSymbolAddress(&pq, g_q);
    cudaGetSymbolAddress(&pk, g_k);
    cudaGetSymbolAddress(&pv, g_v);
    cudaGetSymbolAddress(&pxhi, g_xhi);
    cudaGetSymbolAddress(&pxlo, g_xlo);
    cudaGetSymbolAddress(&pohhi, g_ohhi);
    cudaGetSymbolAddress(&pohlo, g_ohlo);
    cudaGetSymbolAddress(&pwhi, g_whi);
    cudaGetSymbolAddress(&pwlo, g_wlo);

    __nv_bfloat16* whi = (__nv_bfloat16*)pwhi;
    __nv_bfloat16* wlo = (__nv_bfloat16*)pwlo;

    // allow 80KB dynamic smem (idempotent; capture-safe, not a stream op)
    cudaFuncSetAttribute(mma_gemm, cudaFuncAttributeMaxDynamicSharedMemorySize,
                         GSMEM_BYTES);

    // 1) splits
    {
        int n4 = (NTOK * NE) / 4;
        split_kernel<<<n4 / 256, 256>>>(x, (__nv_bfloat16*)pxhi, (__nv_bfloat16*)pxlo, n4);
        int w4 = (NE * NE) / 4;
        split_kernel<<<w4 / 256, 256>>>(Wq, whi + 0 * NE * NE, wlo + 0 * NE * NE, w4);
        split_kernel<<<w4 / 256, 256>>>(Wk, whi + 1 * NE * NE, wlo + 1 * NE * NE, w4);
        split_kernel<<<w4 / 256, 256>>>(Wv, whi + 2 * NE * NE, wlo + 2 * NE * NE, w4);
        split_kernel<<<w4 / 256, 256>>>(Wo, whi + 3 * NE * NE, wlo + 3 * NE * NE, w4);
    }

    // 2) fused QKV projections (tensor cores, z = proj)
    ProjArg aq = { whi + 0 * NE * NE, wlo + 0 * NE * NE, bq, (float*)pq, 1 };
    ProjArg ak = { whi + 1 * NE * NE, wlo + 1 * NE * NE, bk, (float*)pk, 1 };
    ProjArg av = { whi + 2 * NE * NE, wlo + 2 * NE * NE, bv, (float*)pv, 0 };
    {
        dim3 grid(NE / 128, NTOK / 128, 3);
        mma_gemm<<<grid, 256, GSMEM_BYTES>>>((const __nv_bfloat16*)pxhi,
                                             (const __nv_bfloat16*)pxlo,
                                             aq, ak, av);
    }

    // 3) linear attention (emits bf16 hi/lo for the O GEMM)
    linattn_kernel<<<NB * NR * NH, 256>>>((const float*)pq, (const float*)pk,
                                          (const float*)pv,
                                          (__nv_bfloat16*)pohhi, (__nv_bfloat16*)pohlo);

    // 4) output projection
    ProjArg ao = { whi + 3 * NE * NE, wlo + 3 * NE * NE, bo, out, 0 };
    {
        dim3 grid(NE / 128, NTOK / 128, 1);
        mma_gemm<<<grid, 256, GSMEM_BYTES>>>((const __nv_bfloat16*)pohhi,
                                             (const __nv_bfloat16*)pohlo,
                                             ao, ao, ao);
    }
}